// round 6
// baseline (speedup 1.0000x reference)
#include <cuda_runtime.h>
#include <math.h>

// Problem constants
#define NB    8
#define C     528
#define T     16
#define HH    32
#define WW    32
#define R     1024
#define OUTB  8
#define SR    2
#define SCALE (1.0f/16.0f)

#define ROIS  8      // rois per block in fused kernel

// NHWC feature scratch: [b][y][x][c]
__device__ float g_feat[NB * HH * WW * C];

// ---------------------------------------------------------------------------
// Kernel 1: temporal mean + NCHW -> NHWC transpose (coalesced both ways)
// ---------------------------------------------------------------------------
__global__ void mean_t_transpose_kernel(const float* __restrict__ x)
{
    __shared__ float tile[32][33];

    const int by = blockIdx.x;          // b*32 + y
    const int b  = by >> 5;
    const int y  = by & 31;
    const int cchunk = blockIdx.y;

    const int tx = threadIdx.x;
    const int ty = threadIdx.y;

    const int c = cchunk * 32 + ty;
    if (c < C) {
        const float* p = x + (((size_t)(b * C + c) * T) * HH + y) * WW + tx;
        float s0 = 0.f, s1 = 0.f;
        #pragma unroll
        for (int t = 0; t < T; t += 2) {
            s0 += __ldcs(p + (size_t)t       * (HH * WW));
            s1 += __ldcs(p + (size_t)(t + 1) * (HH * WW));
        }
        tile[ty][tx] = (s0 + s1) * (1.0f / T);
    }
    __syncthreads();

    const int c2 = cchunk * 32 + tx;
    if (c2 < C) {
        g_feat[(((size_t)(b * HH + y)) * WW + ty) * C + c2] = tile[tx][ty];
    }
}

// ---------------------------------------------------------------------------
// Kernel 2: fused ROI-align + MLP, 8 rois per block (W1 amortization).
// grid: R/ROIS = 128, block: 512
// ---------------------------------------------------------------------------
__global__ __launch_bounds__(512)
void roi_mlp_fused_kernel(const float* __restrict__ bbox,
                          const float* __restrict__ W1, const float* __restrict__ b1,
                          const float* __restrict__ W2, const float* __restrict__ b2,
                          const float* __restrict__ W3, const float* __restrict__ b3,
                          float* __restrict__ out)
{
    __shared__ float sAx[ROIS][32];
    __shared__ float sAy[ROIS][32];
    __shared__ int   sB[ROIS];
    __shared__ short sXlo[ROIS], sXhi[ROIS], sYlo[ROIS], sYhi[ROIS];
    __shared__ float sPooled[ROIS][C];
    __shared__ float sPart1[4][ROIS][128];
    __shared__ float sH1[ROIS][128];
    __shared__ float sPart2[2][ROIS][32];
    __shared__ float sH2[ROIS][32];

    const int tid  = threadIdx.x;
    const int roi0 = blockIdx.x * ROIS;

    // zero axis weights: ROIS*32*2 = 512 entries, one per thread
    {
        const int r = tid >> 6;          // 0..7
        const int k = tid & 63;
        if (k < 32) sAx[r][k] = 0.f;
        else        sAy[r][k - 32] = 0.f;
    }
    __syncthreads();

    // Phase A: separable axis weights. 16 threads = 8 rois x 2 axes.
    if (tid < ROIS * 2) {
        const int r    = tid >> 1;
        const int axis = tid & 1;        // 0 = x, 1 = y
        const float* bb = bbox + (roi0 + r) * 5;
        if (axis == 0) sB[r] = (int)bb[0];
        float* A = axis ? sAy[r] : sAx[r];
        const float lo_c = bb[1 + axis] * SCALE - 0.5f;
        const float hi_c = bb[3 + axis] * SCALE - 0.5f;
        const float step = (hi_c - lo_c) * (1.0f / (OUTB * SR));
        int lo = 32, hi = -1;
        #pragma unroll
        for (int s = 0; s < 16; s++) {
            const float v = lo_c + ((float)s + 0.5f) * step;
            const bool valid = (v >= -1.0f) && (v <= 32.0f);
            float vc   = fminf(fmaxf(v, 0.0f), 31.0f);
            float lof  = floorf(vc);
            float frac = vc - lof;
            int ilo = (int)lof;
            int ihi = min(ilo + 1, 31);
            if (valid) {
                A[ilo] += 1.0f - frac;
                A[ihi] += frac;
                lo = min(lo, ilo);
                hi = max(hi, ihi);
            }
        }
        if (hi < 0) { lo = 1; hi = 0; }
        if (axis) { sYlo[r] = (short)lo; sYhi[r] = (short)hi; }
        else      { sXlo[r] = (short)lo; sXhi[r] = (short)hi; }
    }
    __syncthreads();

    // Phase B: pooled[r][c], flattened over (r, c) for balance + ILP
    for (int u = tid; u < ROIS * C; u += 512) {
        const int r = u / C;
        const int c = u - r * C;
        const int b   = sB[r];
        const int xlo = sXlo[r], xhi = sXhi[r];
        const int ylo = sYlo[r], yhi = sYhi[r];
        float acc = 0.f;
        for (int y = ylo; y <= yhi; y++) {
            const float ay = sAy[r][y];
            const float* row = g_feat + (((size_t)(b * HH + y)) * WW) * C + c;
            float rs = 0.f;
            for (int xp = xlo; xp <= xhi; xp++)
                rs = fmaf(sAx[r][xp], row[(size_t)xp * C], rs);
            acc = fmaf(ay, rs, acc);
        }
        sPooled[r][c] = acc * (1.0f / 256.0f);
    }
    __syncthreads();

    // Phase C: layer 1 (528 -> 128, relu), W1 loaded ONCE per block-part,
    // reused across all 8 rois. 512 threads = 4 c-parts x 128 outputs.
    {
        const int part = tid >> 7;        // 0..3, 132 channels each
        const int j    = tid & 127;
        const int c0 = part * 132;
        float acc[ROIS];
        #pragma unroll
        for (int r = 0; r < ROIS; r++) acc[r] = 0.f;
        for (int c = c0; c < c0 + 132; c++) {
            const float w = W1[c * 128 + j];
            #pragma unroll
            for (int r = 0; r < ROIS; r++)
                acc[r] = fmaf(sPooled[r][c], w, acc[r]);
        }
        #pragma unroll
        for (int r = 0; r < ROIS; r++)
            sPart1[part][r][j] = acc[r];
    }
    __syncthreads();
    // reduce parts: 1024 outputs / 512 threads = 2 each
    {
        #pragma unroll
        for (int u = tid; u < ROIS * 128; u += 512) {
            const int r = u >> 7;
            const int j = u & 127;
            float acc = (sPart1[0][r][j] + sPart1[1][r][j])
                      + (sPart1[2][r][j] + sPart1[3][r][j]) + b1[j];
            sH1[r][j] = fmaxf(acc, 0.f);
        }
    }
    __syncthreads();

    // Phase D: layer 2 (128 -> 32). 512 threads = 2 k-parts x 8 rois x 32 j.
    {
        const int part = tid >> 8;        // 0..1, 64 k each
        const int r    = (tid >> 5) & 7;
        const int j    = tid & 31;
        const int k0 = part * 64;
        float a0 = 0.f, a1 = 0.f;
        #pragma unroll
        for (int k = k0; k < k0 + 64; k += 2) {
            a0 = fmaf(sH1[r][k],     W2[(k)     * 32 + j], a0);
            a1 = fmaf(sH1[r][k + 1], W2[(k + 1) * 32 + j], a1);
        }
        sPart2[part][r][j] = a0 + a1;
    }
    __syncthreads();
    if (tid < ROIS * 32) {
        const int r = tid >> 5;
        const int j = tid & 31;
        sH2[r][j] = sPart2[0][r][j] + sPart2[1][r][j] + b2[j];
    }
    __syncthreads();

    // Phase E: layer 3 + sigmoid. 8 warps, one roi each, butterfly reduce.
    if (tid < ROIS * 32) {
        const int r    = tid >> 5;
        const int lane = tid & 31;
        float v = sH2[r][lane] * W3[lane];
        #pragma unroll
        for (int off = 16; off > 0; off >>= 1)
            v += __shfl_xor_sync(0xFFFFFFFF, v, off);
        if (lane == 0)
            out[roi0 + r] = 1.0f / (1.0f + expf(-(v + b3[0])));
    }
}

// ---------------------------------------------------------------------------
extern "C" void kernel_launch(void* const* d_in, const int* in_sizes, int n_in,
                              void* d_out, int out_size)
{
    const float* x    = (const float*)d_in[0];
    const float* bbox = (const float*)d_in[1];
    const float* W1   = (const float*)d_in[2];
    const float* b1   = (const float*)d_in[3];
    const float* W2   = (const float*)d_in[4];
    const float* b2   = (const float*)d_in[5];
    const float* W3   = (const float*)d_in[6];
    const float* b3   = (const float*)d_in[7];
    float* out = (float*)d_out;

    dim3 g1(NB * HH, (C + 31) / 32);
    dim3 t1(32, 32);
    mean_t_transpose_kernel<<<g1, t1>>>(x);

    roi_mlp_fused_kernel<<<R / ROIS, 512>>>(bbox, W1, b1, W2, b2, W3, b3, out);
}

// round 7
// speedup vs baseline: 1.9777x; 1.9777x over previous
#include <cuda_runtime.h>
#include <math.h>

// Problem constants
#define NB    8
#define C     528
#define CV    (C/4)          // 132 float4 groups
#define T     16
#define HH    32
#define WW    32
#define R     1024
#define OUTB  8
#define SR    2
#define SCALE (1.0f/16.0f)

// NHWC feature scratch: [b][y][x][c]
__device__ float g_feat[NB * HH * WW * C];
// pooled scratch: [roi][c]
__device__ float g_pooled[R * C];

// ---------------------------------------------------------------------------
// Kernel 1: temporal mean + NCHW -> NHWC transpose (coalesced both ways)
// ---------------------------------------------------------------------------
__global__ void mean_t_transpose_kernel(const float* __restrict__ x)
{
    __shared__ float tile[32][33];

    const int by = blockIdx.x;          // b*32 + y
    const int b  = by >> 5;
    const int y  = by & 31;
    const int cchunk = blockIdx.y;

    const int tx = threadIdx.x;
    const int ty = threadIdx.y;

    const int c = cchunk * 32 + ty;
    if (c < C) {
        const float* p = x + (((size_t)(b * C + c) * T) * HH + y) * WW + tx;
        float s0 = 0.f, s1 = 0.f;
        #pragma unroll
        for (int t = 0; t < T; t += 2) {
            s0 += __ldcs(p + (size_t)t       * (HH * WW));
            s1 += __ldcs(p + (size_t)(t + 1) * (HH * WW));
        }
        tile[ty][tx] = (s0 + s1) * (1.0f / T);
    }
    __syncthreads();

    const int c2 = cchunk * 32 + tx;
    if (c2 < C) {
        g_feat[(((size_t)(b * HH + y)) * WW + ty) * C + c2] = tile[tx][ty];
    }
}

// ---------------------------------------------------------------------------
// Kernel 2: ROI pooling, separable weights, float4 gather.
// grid: R, block: 160 (132 active in gather)
// ---------------------------------------------------------------------------
__global__ __launch_bounds__(160)
void roi_pool_kernel(const float* __restrict__ bbox)
{
    __shared__ float sAx[32];
    __shared__ float sAy[32];
    __shared__ int   sB;
    __shared__ int   sXlo, sXhi, sYlo, sYhi;

    const int tid = threadIdx.x;
    const int roi = blockIdx.x;

    if (tid < 32)       sAx[tid]      = 0.f;
    else if (tid < 64)  sAy[tid - 32] = 0.f;
    __syncthreads();

    // Phase A: per-axis separable weights (2 threads, deterministic serial)
    if (tid < 2) {
        const float* bb = bbox + roi * 5;
        if (tid == 0) sB = (int)bb[0];
        float* A = tid ? sAy : sAx;
        const float lo_c = bb[1 + tid] * SCALE - 0.5f;
        const float hi_c = bb[3 + tid] * SCALE - 0.5f;
        const float step = (hi_c - lo_c) * (1.0f / (OUTB * SR));
        int lo = 32, hi = -1;
        #pragma unroll
        for (int s = 0; s < 16; s++) {
            const float v = lo_c + ((float)s + 0.5f) * step;
            const bool valid = (v >= -1.0f) && (v <= 32.0f);
            float vc   = fminf(fmaxf(v, 0.0f), 31.0f);
            float lof  = floorf(vc);
            float frac = vc - lof;
            int ilo = (int)lof;
            int ihi = min(ilo + 1, 31);
            if (valid) {
                A[ilo] += 1.0f - frac;
                A[ihi] += frac;
                lo = min(lo, ilo);
                hi = max(hi, ihi);
            }
        }
        if (hi < 0) { lo = 1; hi = 0; }
        if (tid) { sYlo = lo; sYhi = hi; }
        else     { sXlo = lo; sXhi = hi; }
    }
    __syncthreads();

    // Phase B: gather. One float4 channel-group per thread.
    if (tid < CV) {
        const int b   = sB;
        const int xlo = sXlo, xhi = sXhi;
        const int ylo = sYlo, yhi = sYhi;
        const float4* f4 = (const float4*)g_feat;

        float4 acc = make_float4(0.f, 0.f, 0.f, 0.f);
        for (int y = ylo; y <= yhi; y++) {
            const float ay = sAy[y];
            const float4* rowb = f4 + ((size_t)(b * HH + y) * WW) * CV + tid;
            float4 rs = make_float4(0.f, 0.f, 0.f, 0.f);
            for (int xp = xlo; xp <= xhi; xp++) {
                const float ax = sAx[xp];
                const float4 v = rowb[(size_t)xp * CV];
                rs.x = fmaf(ax, v.x, rs.x);
                rs.y = fmaf(ax, v.y, rs.y);
                rs.z = fmaf(ax, v.z, rs.z);
                rs.w = fmaf(ax, v.w, rs.w);
            }
            acc.x = fmaf(ay, rs.x, acc.x);
            acc.y = fmaf(ay, rs.y, acc.y);
            acc.z = fmaf(ay, rs.z, acc.z);
            acc.w = fmaf(ay, rs.w, acc.w);
        }
        acc.x *= (1.0f / 256.0f);
        acc.y *= (1.0f / 256.0f);
        acc.z *= (1.0f / 256.0f);
        acc.w *= (1.0f / 256.0f);
        ((float4*)g_pooled)[(size_t)roi * CV + tid] = acc;
    }
}

// ---------------------------------------------------------------------------
// Kernel 3: MLP 528 -> 128 (relu) -> 32 -> 1 (sigmoid), 8 rois per block.
// grid: R/8 = 128, block: 256.
// Layer 1: register-tiled GEMM. Warp layout: lane = part*4 + jq.
//   j4 = warp*4 + jq (float4 of j), part in 0..7 covers 66 channels each.
//   One W1 LDG.128 feeds 32 FMAs (8 rois x float4). shfl-reduce over parts.
// ---------------------------------------------------------------------------
#define MR 8

__global__ __launch_bounds__(256)
void mlp_kernel(const float* __restrict__ W1, const float* __restrict__ b1,
                const float* __restrict__ W2, const float* __restrict__ b2,
                const float* __restrict__ W3, const float* __restrict__ b3,
                float* __restrict__ out)
{
    __shared__ float sPooled[MR][C];   // 16.9 KB
    __shared__ float sH1[MR][128];     // 4 KB
    __shared__ float sH2[MR][32];      // 1 KB

    const int tid  = threadIdx.x;
    const int roi0 = blockIdx.x * MR;

    // load pooled tile (contiguous, coalesced float4)
    {
        const float4* gp4 = (const float4*)g_pooled + (size_t)roi0 * CV;
        float4* sp4 = (float4*)&sPooled[0][0];
        #pragma unroll
        for (int u = tid; u < MR * CV; u += 256)
            sp4[u] = gp4[u];
    }
    __syncthreads();

    // Layer 1
    {
        const int lane = tid & 31;
        const int w    = tid >> 5;            // warp 0..7
        const int part = lane >> 2;           // 0..7
        const int jq   = lane & 3;
        const int j4   = w * 4 + jq;          // 0..31 (float4 index over j)
        const int c0   = part * 66;

        const float4* W1_4 = (const float4*)W1;   // [c][32]

        float4 a[MR];
        #pragma unroll
        for (int r = 0; r < MR; r++) a[r] = make_float4(0.f, 0.f, 0.f, 0.f);

        #pragma unroll 2
        for (int c = c0; c < c0 + 66; c++) {
            const float4 wv = W1_4[c * 32 + j4];
            #pragma unroll
            for (int r = 0; r < MR; r++) {
                const float p = sPooled[r][c];
                a[r].x = fmaf(p, wv.x, a[r].x);
                a[r].y = fmaf(p, wv.y, a[r].y);
                a[r].z = fmaf(p, wv.z, a[r].z);
                a[r].w = fmaf(p, wv.w, a[r].w);
            }
        }

        // butterfly-reduce over part bits (lane bits 2..4)
        #pragma unroll
        for (int off = 4; off <= 16; off <<= 1) {
            #pragma unroll
            for (int r = 0; r < MR; r++) {
                a[r].x += __shfl_xor_sync(0xFFFFFFFF, a[r].x, off);
                a[r].y += __shfl_xor_sync(0xFFFFFFFF, a[r].y, off);
                a[r].z += __shfl_xor_sync(0xFFFFFFFF, a[r].z, off);
                a[r].w += __shfl_xor_sync(0xFFFFFFFF, a[r].w, off);
            }
        }

        if (part == 0) {
            const float4 bb = ((const float4*)b1)[j4];
            #pragma unroll
            for (int r = 0; r < MR; r++) {
                float4 h;
                h.x = fmaxf(a[r].x + bb.x, 0.f);
                h.y = fmaxf(a[r].y + bb.y, 0.f);
                h.z = fmaxf(a[r].z + bb.z, 0.f);
                h.w = fmaxf(a[r].w + bb.w, 0.f);
                ((float4*)&sH1[r][0])[j4] = h;
            }
        }
    }
    __syncthreads();

    // Layer 2: 256 threads = 8 rois x 32 outputs
    {
        const int r = tid >> 5;
        const int j = tid & 31;
        const float* h = sH1[r];
        float a0 = 0.f, a1 = 0.f;
        #pragma unroll
        for (int k = 0; k < 128; k += 2) {
            a0 = fmaf(h[k],     W2[(k)     * 32 + j], a0);
            a1 = fmaf(h[k + 1], W2[(k + 1) * 32 + j], a1);
        }
        sH2[r][j] = a0 + a1 + b2[j];
    }
    __syncthreads();

    // Layer 3 + sigmoid: one warp per roi
    {
        const int r    = tid >> 5;
        const int lane = tid & 31;
        float v = sH2[r][lane] * W3[lane];
        #pragma unroll
        for (int off = 16; off > 0; off >>= 1)
            v += __shfl_xor_sync(0xFFFFFFFF, v, off);
        if (lane == 0)
            out[roi0 + r] = 1.0f / (1.0f + expf(-(v + b3[0])));
    }
}

// ---------------------------------------------------------------------------
extern "C" void kernel_launch(void* const* d_in, const int* in_sizes, int n_in,
                              void* d_out, int out_size)
{
    const float* x    = (const float*)d_in[0];
    const float* bbox = (const float*)d_in[1];
    const float* W1   = (const float*)d_in[2];
    const float* b1   = (const float*)d_in[3];
    const float* W2   = (const float*)d_in[4];
    const float* b2   = (const float*)d_in[5];
    const float* W3   = (const float*)d_in[6];
    const float* b3   = (const float*)d_in[7];
    float* out = (float*)d_out;

    dim3 g1(NB * HH, (C + 31) / 32);
    dim3 t1(32, 32);
    mean_t_transpose_kernel<<<g1, t1>>>(x);

    roi_pool_kernel<<<R, 160>>>(bbox);

    mlp_kernel<<<R / MR, 256>>>(W1, b1, W2, b2, W3, b3, out);
}

// round 8
// speedup vs baseline: 2.0827x; 1.0531x over previous
#include <cuda_runtime.h>
#include <cuda_fp16.h>
#include <math.h>

// Problem constants
#define NB    8
#define C     528
#define CV4   (C/4)          // 132 groups of 4 channels
#define T     16
#define HH    32
#define WW    32
#define R     1024
#define OUTB  8
#define SR    2
#define SCALE (1.0f/16.0f)

// NHWC feature scratch in fp16: [b][y][x][c]
__device__ __half g_feat_h[NB * HH * WW * C];
// pooled scratch fp32: [roi][c]
__device__ float g_pooled[R * C];

// ---------------------------------------------------------------------------
// Kernel 1: temporal mean + NCHW -> NHWC transpose, fp32 accum, fp16 store
// grid: (NB*HH, ceil(C/32)), block: (32,32)
// ---------------------------------------------------------------------------
__global__ void mean_t_transpose_kernel(const float* __restrict__ x)
{
    __shared__ float tile[32][33];

    const int by = blockIdx.x;          // b*32 + y
    const int b  = by >> 5;
    const int y  = by & 31;
    const int cchunk = blockIdx.y;

    const int tx = threadIdx.x;
    const int ty = threadIdx.y;

    const int c = cchunk * 32 + ty;
    if (c < C) {
        const float* p = x + (((size_t)(b * C + c) * T) * HH + y) * WW + tx;
        float s0 = 0.f, s1 = 0.f;
        #pragma unroll
        for (int t = 0; t < T; t += 2) {
            s0 += __ldcs(p + (size_t)t       * (HH * WW));
            s1 += __ldcs(p + (size_t)(t + 1) * (HH * WW));
        }
        tile[ty][tx] = (s0 + s1) * (1.0f / T);
    }
    __syncthreads();

    const int c2 = cchunk * 32 + tx;
    if (c2 < C) {
        g_feat_h[(((size_t)(b * HH + y)) * WW + ty) * C + c2] =
            __float2half(tile[tx][ty]);
    }
}

// ---------------------------------------------------------------------------
// Kernel 2: ROI pooling, separable weights (per-bin deterministic build),
// fp16 gather (uint2 = 4 channels per load). grid: R, block: 160.
// ---------------------------------------------------------------------------
__global__ __launch_bounds__(160)
void roi_pool_kernel(const float* __restrict__ bbox)
{
    __shared__ float sAx[32];
    __shared__ float sAy[32];
    __shared__ int   sB;
    __shared__ int   sXlo, sXhi, sYlo, sYhi;

    const int tid = threadIdx.x;
    const int roi = blockIdx.x;

    // Phase A: per-BIN weight computation. warp0 = x-axis, warp1 = y-axis.
    // Bit-deterministic: each bin sums its own contributions, no RMW races.
    if (tid < 64) {
        const int axis = tid >> 5;       // 0 = x, 1 = y
        const int bin  = tid & 31;
        const float* bb = bbox + roi * 5;
        if (tid == 0) sB = (int)bb[0];

        const float lo_c = bb[1 + axis] * SCALE - 0.5f;
        const float hi_c = bb[3 + axis] * SCALE - 0.5f;
        const float step = (hi_c - lo_c) * (1.0f / (OUTB * SR));

        float w = 0.f;
        #pragma unroll
        for (int s = 0; s < 16; s++) {
            const float v = lo_c + ((float)s + 0.5f) * step;
            const bool valid = (v >= -1.0f) && (v <= 32.0f);
            float vc   = fminf(fmaxf(v, 0.0f), 31.0f);
            float lof  = floorf(vc);
            float frac = vc - lof;
            int ilo = (int)lof;
            int ihi = min(ilo + 1, 31);
            if (valid) {
                if (ilo == bin) w += 1.0f - frac;
                if (ihi == bin) w += frac;
            }
        }
        if (axis) sAy[bin] = w; else sAx[bin] = w;

        // support bounds via ballot over nonzero bins
        unsigned m = __ballot_sync(0xFFFFFFFF, w != 0.f);
        if (bin == 0) {
            int lo, hi;
            if (m == 0u) { lo = 1; hi = 0; }
            else { lo = __ffs(m) - 1; hi = 31 - __clz(m); }
            if (axis) { sYlo = lo; sYhi = hi; }
            else      { sXlo = lo; sXhi = hi; }
        }
    }
    __syncthreads();

    // Phase B: gather. One uint2 (4 fp16 channels) per thread per pixel.
    if (tid < CV4) {
        const int b   = sB;
        const int xlo = sXlo, xhi = sXhi;
        const int ylo = sYlo, yhi = sYhi;
        const uint2* fh = (const uint2*)g_feat_h;   // 4 halves per uint2

        float4 acc = make_float4(0.f, 0.f, 0.f, 0.f);
        for (int y = ylo; y <= yhi; y++) {
            const float ay = sAy[y];
            const uint2* rowb = fh + ((size_t)(b * HH + y) * WW) * CV4 + tid;
            float4 rs = make_float4(0.f, 0.f, 0.f, 0.f);
            for (int xp = xlo; xp <= xhi; xp++) {
                const float ax = sAx[xp];
                const uint2 raw = rowb[(size_t)xp * CV4];
                const float2 f01 = __half22float2(*(const __half2*)&raw.x);
                const float2 f23 = __half22float2(*(const __half2*)&raw.y);
                rs.x = fmaf(ax, f01.x, rs.x);
                rs.y = fmaf(ax, f01.y, rs.y);
                rs.z = fmaf(ax, f23.x, rs.z);
                rs.w = fmaf(ax, f23.y, rs.w);
            }
            acc.x = fmaf(ay, rs.x, acc.x);
            acc.y = fmaf(ay, rs.y, acc.y);
            acc.z = fmaf(ay, rs.z, acc.z);
            acc.w = fmaf(ay, rs.w, acc.w);
        }
        acc.x *= (1.0f / 256.0f);
        acc.y *= (1.0f / 256.0f);
        acc.z *= (1.0f / 256.0f);
        acc.w *= (1.0f / 256.0f);
        ((float4*)g_pooled)[(size_t)roi * CV4 + tid] = acc;
    }
}

// ---------------------------------------------------------------------------
// Kernel 3: MLP 528 -> 128 (relu) -> 32 -> 1 (sigmoid), 8 rois per block.
// grid: R/8 = 128, block: 256. Layer 1 register-tiled; W1 LDG.128 feeds
// 32 FMAs; shfl-reduce over c-parts.
// ---------------------------------------------------------------------------
#define MR 8

__global__ __launch_bounds__(256)
void mlp_kernel(const float* __restrict__ W1, const float* __restrict__ b1,
                const float* __restrict__ W2, const float* __restrict__ b2,
                const float* __restrict__ W3, const float* __restrict__ b3,
                float* __restrict__ out)
{
    __shared__ float sPooled[MR][C];
    __shared__ float sH1[MR][128];
    __shared__ float sH2[MR][32];

    const int tid  = threadIdx.x;
    const int roi0 = blockIdx.x * MR;

    {
        const float4* gp4 = (const float4*)g_pooled + (size_t)roi0 * CV4;
        float4* sp4 = (float4*)&sPooled[0][0];
        #pragma unroll
        for (int u = tid; u < MR * CV4; u += 256)
            sp4[u] = gp4[u];
    }
    __syncthreads();

    // Layer 1
    {
        const int lane = tid & 31;
        const int w    = tid >> 5;            // warp 0..7
        const int part = lane >> 2;           // 0..7 (c-part, 66 each)
        const int jq   = lane & 3;
        const int j4   = w * 4 + jq;          // float4 index over j (0..31)
        const int c0   = part * 66;

        const float4* W1_4 = (const float4*)W1;   // [c][32]

        float4 a[MR];
        #pragma unroll
        for (int r = 0; r < MR; r++) a[r] = make_float4(0.f, 0.f, 0.f, 0.f);

        #pragma unroll 2
        for (int c = c0; c < c0 + 66; c++) {
            const float4 wv = W1_4[c * 32 + j4];
            #pragma unroll
            for (int r = 0; r < MR; r++) {
                const float p = sPooled[r][c];
                a[r].x = fmaf(p, wv.x, a[r].x);
                a[r].y = fmaf(p, wv.y, a[r].y);
                a[r].z = fmaf(p, wv.z, a[r].z);
                a[r].w = fmaf(p, wv.w, a[r].w);
            }
        }

        #pragma unroll
        for (int off = 4; off <= 16; off <<= 1) {
            #pragma unroll
            for (int r = 0; r < MR; r++) {
                a[r].x += __shfl_xor_sync(0xFFFFFFFF, a[r].x, off);
                a[r].y += __shfl_xor_sync(0xFFFFFFFF, a[r].y, off);
                a[r].z += __shfl_xor_sync(0xFFFFFFFF, a[r].z, off);
                a[r].w += __shfl_xor_sync(0xFFFFFFFF, a[r].w, off);
            }
        }

        if (part == 0) {
            const float4 bb = ((const float4*)b1)[j4];
            #pragma unroll
            for (int r = 0; r < MR; r++) {
                float4 h;
                h.x = fmaxf(a[r].x + bb.x, 0.f);
                h.y = fmaxf(a[r].y + bb.y, 0.f);
                h.z = fmaxf(a[r].z + bb.z, 0.f);
                h.w = fmaxf(a[r].w + bb.w, 0.f);
                ((float4*)&sH1[r][0])[j4] = h;
            }
        }
    }
    __syncthreads();

    // Layer 2
    {
        const int r = tid >> 5;
        const int j = tid & 31;
        const float* h = sH1[r];
        float a0 = 0.f, a1 = 0.f;
        #pragma unroll
        for (int k = 0; k < 128; k += 2) {
            a0 = fmaf(h[k],     W2[(k)     * 32 + j], a0);
            a1 = fmaf(h[k + 1], W2[(k + 1) * 32 + j], a1);
        }
        sH2[r][j] = a0 + a1 + b2[j];
    }
    __syncthreads();

    // Layer 3 + sigmoid
    {
        const int r    = tid >> 5;
        const int lane = tid & 31;
        float v = sH2[r][lane] * W3[lane];
        #pragma unroll
        for (int off = 16; off > 0; off >>= 1)
            v += __shfl_xor_sync(0xFFFFFFFF, v, off);
        if (lane == 0)
            out[roi0 + r] = 1.0f / (1.0f + expf(-(v + b3[0])));
    }
}

// ---------------------------------------------------------------------------
extern "C" void kernel_launch(void* const* d_in, const int* in_sizes, int n_in,
                              void* d_out, int out_size)
{
    const float* x    = (const float*)d_in[0];
    const float* bbox = (const float*)d_in[1];
    const float* W1   = (const float*)d_in[2];
    const float* b1   = (const float*)d_in[3];
    const float* W2   = (const float*)d_in[4];
    const float* b2   = (const float*)d_in[5];
    const float* W3   = (const float*)d_in[6];
    const float* b3   = (const float*)d_in[7];
    float* out = (float*)d_out;

    dim3 g1(NB * HH, (C + 31) / 32);
    dim3 t1(32, 32);
    mean_t_transpose_kernel<<<g1, t1>>>(x);

    roi_pool_kernel<<<R, 160>>>(bbox);

    mlp_kernel<<<R / MR, 256>>>(W1, b1, W2, b2, W3, b3, out);
}